// round 16
// baseline (speedup 1.0000x reference)
#include <cuda_runtime.h>
#include <cuda_fp16.h>
#include <cstdint>

#define B_    4096
#define NCH   32
#define SIZE_ 512
#define CH    256
#define KTOT  768
#define KCH   32
#define NITER (KTOT / KCH)   // 24 (iou kernel)
#define KCH2  64
#define NIT2  (KTOT / KCH2)  // 12 (fgate kernel)

// scratch
__device__ float g_fc[B_ * CH];                 // sum_n sigmoid(f)*c_k
__device__ float g_logits[3 * B_ * CH];         // i/o/u raw logits
__device__ __half g_wfh[CH * KTOT];             // fp16 packed [Wf | Uf]  [256][768]

// ---------------------------------------------------------------------------
// helpers
// ---------------------------------------------------------------------------
__device__ __forceinline__ float sigf(float x) { return 1.0f / (1.0f + __expf(-x)); }

__device__ __forceinline__ uint32_t s2u(const void* p) {
    uint32_t a;
    asm("{ .reg .u64 t; cvta.to.shared.u64 t, %1; cvt.u32.u64 %0, t; }" : "=r"(a) : "l"(p));
    return a;
}
__device__ __forceinline__ unsigned packh(float lo, float hi) {
    __half2 h = __floats2half2_rn(lo, hi);
    return *reinterpret_cast<unsigned*>(&h);
}
__device__ __forceinline__ void cp16(uint32_t dst, const void* src) {
    asm volatile("cp.async.cg.shared.global [%0], [%1], 16;" :: "r"(dst), "l"(src) : "memory");
}
__device__ __forceinline__ void cp_commit() {
    asm volatile("cp.async.commit_group;" ::: "memory");
}
__device__ __forceinline__ void cp_wait0() {
    asm volatile("cp.async.wait_group 0;" ::: "memory");
}
__device__ __forceinline__ void ldsm4(unsigned* r, uint32_t addr) {
    asm volatile("ldmatrix.sync.aligned.m8n8.x4.shared.b16 {%0,%1,%2,%3}, [%4];"
                 : "=r"(r[0]), "=r"(r[1]), "=r"(r[2]), "=r"(r[3]) : "r"(addr));
}
__device__ __forceinline__ void sts128(uint32_t addr, unsigned a, unsigned b, unsigned c, unsigned d) {
    asm volatile("st.shared.v4.b32 [%0], {%1,%2,%3,%4};"
                 :: "r"(addr), "r"(a), "r"(b), "r"(c), "r"(d) : "memory");
}
__device__ __forceinline__ void mma16(float* d, const unsigned* a, const unsigned* b) {
    asm volatile(
        "mma.sync.aligned.m16n8k16.row.col.f32.f16.f16.f32 "
        "{%0,%1,%2,%3}, {%4,%5,%6,%7}, {%8,%9}, {%0,%1,%2,%3};\n"
        : "+f"(d[0]), "+f"(d[1]), "+f"(d[2]), "+f"(d[3])
        : "r"(a[0]), "r"(a[1]), "r"(a[2]), "r"(a[3]), "r"(b[0]), "r"(b[1]));
}

// 64B-row swizzle (iou kernel)
__device__ __forceinline__ uint32_t swz(int row, int ch) {
    return (uint32_t)row * 64u + ((uint32_t)(ch ^ ((row >> 1) & 3)) << 4);
}
// 128B-row swizzle (fgate kernel): classic SW128 16B-chunk xor
__device__ __forceinline__ uint32_t swz128(int row, int ch) {
    return (uint32_t)row * 128u + ((uint32_t)(ch ^ (row & 7)) << 4);
}

// ---------------------------------------------------------------------------
// Kernel 0: pack + convert f-gate weights to fp16
// ---------------------------------------------------------------------------
__global__ void __launch_bounds__(256) wcvt_kernel(const float* __restrict__ Wf,
                                                   const float* __restrict__ Uf) {
    const int r = blockIdx.x;
    for (int it = 0; it < 3; it++) {
        const int k = it * 256 + threadIdx.x;
        const float v = (k < SIZE_) ? Wf[(size_t)r * SIZE_ + k]
                                    : Uf[(size_t)r * CH + (k - SIZE_)];
        g_wfh[(size_t)r * KTOT + k] = __float2half_rn(v);
    }
}

// ---------------------------------------------------------------------------
// Kernel 1: h_tilde[b][c] = sum_n z_children[b][n][c]   (exact fp32)
// ---------------------------------------------------------------------------
__global__ void __launch_bounds__(256) htilde_kernel(const float* __restrict__ zc,
                                                     float* __restrict__ ht) {
    const int b = blockIdx.x;
    const int c = threadIdx.x;
    const float* p = zc + (size_t)b * NCH * SIZE_ + c;
    float s = 0.0f;
#pragma unroll
    for (int n = 0; n < NCH; n++) s += p[(size_t)n * SIZE_];
    ht[(size_t)b * CH + c] = s;
}

// ---------------------------------------------------------------------------
// Kernel 2: f-gate GEMM (131072 x 768 @ 768 x 256) fp16 + fused child
// reduction. EXACT R13 version (best fgate measured: 203us).
// CTA tile M=128 x N=128; K-chunk 64 (12 barriers). 256 threads, 8 warps,
// warp tile 64x32; 2 CTAs/SM.
// ---------------------------------------------------------------------------
#define FG_STG2 32768   // per stage: A 128x128B (16KB) + B 128x128B (16KB)

__global__ void __launch_bounds__(256, 2)
fgate_kernel(const float* __restrict__ zn, const float* __restrict__ zc,
             const float* __restrict__ bfv) {
    extern __shared__ char smem[];
    const uint32_t sb = s2u(smem);

    const int tid  = threadIdx.x;
    const int warp = tid >> 5, lane = tid & 31;
    const int g = lane >> 2, t = lane & 3;
    const int r = lane & 7, l8 = (lane >> 3) & 1, l16 = lane >> 4;
    const int wm = warp >> 2, wn = warp & 3;
    const int rowBase = blockIdx.y * 128;     // child-rows (b*32+n)
    const int colBase = blockIdx.x * 128;     // gate cols

    float acc[4][4][4];
#pragma unroll
    for (int mi = 0; mi < 4; mi++)
#pragma unroll
        for (int ni = 0; ni < 4; ni++)
#pragma unroll
            for (int e = 0; e < 4; e++) acc[mi][ni][e] = 0.0f;

    // staging geometry: unit = 16B fp16 = 8 fp32; rows tRow + 32*i, chunk tCh
    const int tRow = tid >> 3, tCh = tid & 7;
    float4 aS[4][2];

    auto LDG_A = [&](int c) {
        const int kk = c * KCH2 + tCh * 8;
#pragma unroll
        for (int i = 0; i < 4; i++) {
            const int row = rowBase + tRow + 32 * i;
            const float* p = (kk < SIZE_)
                ? zn + (size_t)row * SIZE_ + kk
                : zc + (size_t)row * SIZE_ + (kk - SIZE_);   // h_k
            aS[i][0] = *reinterpret_cast<const float4*>(p);
            aS[i][1] = *reinterpret_cast<const float4*>(p + 4);
        }
    };
    auto STS_A = [&](int buf) {
        const uint32_t a0 = sb + buf * FG_STG2;
#pragma unroll
        for (int i = 0; i < 4; i++) {
            sts128(a0 + swz128(tRow + 32 * i, tCh),
                   packh(aS[i][0].x, aS[i][0].y), packh(aS[i][0].z, aS[i][0].w),
                   packh(aS[i][1].x, aS[i][1].y), packh(aS[i][1].z, aS[i][1].w));
        }
    };
    auto CP_B = [&](int c, int buf) {
        const uint32_t smB = sb + buf * FG_STG2 + 16384;
        const int kk = c * KCH2 + tCh * 8;
#pragma unroll
        for (int i = 0; i < 4; i++) {
            const int row = tRow + 32 * i;
            cp16(smB + swz128(row, tCh), &g_wfh[(size_t)(colBase + row) * KTOT + kk]);
        }
    };

    auto DO_KS = [&](uint32_t smA, uint32_t smB, int ks) {
        unsigned af[4][4];
#pragma unroll
        for (int mi = 0; mi < 4; mi++) {
            const int m = wm * 64 + mi * 16 + l8 * 8 + r;
            ldsm4(af[mi], smA + swz128(m, 2 * ks + l16));
        }
        unsigned bf[4][2];
#pragma unroll
        for (int p = 0; p < 2; p++) {
            const int n = wn * 32 + p * 16 + l16 * 8 + r;
            unsigned tmp[4];
            ldsm4(tmp, smB + swz128(n, 2 * ks + l8));
            bf[2 * p][0] = tmp[0]; bf[2 * p][1] = tmp[1];
            bf[2 * p + 1][0] = tmp[2]; bf[2 * p + 1][1] = tmp[3];
        }
#pragma unroll
        for (int mi = 0; mi < 4; mi++)
#pragma unroll
            for (int ni = 0; ni < 4; ni++) mma16(acc[mi][ni], af[mi], bf[ni]);
    };

    // prologue: chunk0 -> stage0, chunk1 A -> regs
    CP_B(0, 0); cp_commit();
    LDG_A(0);
    STS_A(0);
    LDG_A(1);
    cp_wait0();
    __syncthreads();

    for (int c = 0; c < NIT2; c++) {
        const int buf = c & 1;
        if (c + 1 < NIT2) {
            STS_A(buf ^ 1);          // regs loaded during previous chunk
            CP_B(c + 1, buf ^ 1);
        }
        cp_commit();

        const uint32_t smA = sb + buf * FG_STG2;
        const uint32_t smB = smA + 16384;
        DO_KS(smA, smB, 0);
        if (c + 2 < NIT2) LDG_A(c + 2);   // latency hidden by remaining 3 ks
        DO_KS(smA, smB, 1);
        DO_KS(smA, smB, 2);
        DO_KS(smA, smB, 3);

        cp_wait0();
        __syncthreads();
    }

    // ---- Epilogue: sigmoid(+bias) * c_k, reduce over the 32 children ----
#pragma unroll
    for (int bb2 = 0; bb2 < 2; bb2++) {
        const int bGlob = blockIdx.y * 4 + wm * 2 + bb2;
#pragma unroll
        for (int ni = 0; ni < 4; ni++) {
            const int colG = colBase + wn * 32 + ni * 8 + 2 * t;
            const float2 bias = *reinterpret_cast<const float2*>(bfv + colG);
            float p0 = 0.0f, p1 = 0.0f;
#pragma unroll
            for (int ml = 0; ml < 2; ml++) {
                const int mi = bb2 * 2 + ml;
                const int n0 = ml * 16 + g, n1 = n0 + 8;
                const float2 ck0 = *reinterpret_cast<const float2*>(
                    zc + (size_t)(bGlob * NCH + n0) * SIZE_ + CH + colG);
                const float2 ck1 = *reinterpret_cast<const float2*>(
                    zc + (size_t)(bGlob * NCH + n1) * SIZE_ + CH + colG);
                p0 += sigf(acc[mi][ni][0] + bias.x) * ck0.x + sigf(acc[mi][ni][2] + bias.x) * ck1.x;
                p1 += sigf(acc[mi][ni][1] + bias.y) * ck0.y + sigf(acc[mi][ni][3] + bias.y) * ck1.y;
            }
#pragma unroll
            for (int s = 4; s < 32; s <<= 1) {
                p0 += __shfl_xor_sync(0xffffffffu, p0, s);
                p1 += __shfl_xor_sync(0xffffffffu, p1, s);
            }
            if (g == 0) {
                float2 v; v.x = p0; v.y = p1;
                *reinterpret_cast<float2*>(g_fc + (size_t)bGlob * CH + colG) = v;
            }
        }
    }
}

// ---------------------------------------------------------------------------
// Kernel 3: i/o/u logits (proven R8/R11 version):
// [z0 | h_tilde] (4096x768) @ (768x256) per gate; gate = blockIdx.z.
// ---------------------------------------------------------------------------
#define STG_BYTES 12288

__global__ void __launch_bounds__(256, 2)
iou_gemm_kernel(const float* __restrict__ zn, const float* __restrict__ ht,
                const float* __restrict__ Wi, const float* __restrict__ Ui,
                const float* __restrict__ Wo, const float* __restrict__ Uo,
                const float* __restrict__ Wu, const float* __restrict__ Uu) {
    __shared__ char smem[2 * STG_BYTES];
    const uint32_t sb = s2u(smem);

    const int tid  = threadIdx.x;
    const int warp = tid >> 5, lane = tid & 31;
    const int g = lane >> 2, t = lane & 3;
    const int r = lane & 7, l8 = (lane >> 3) & 1, l16 = lane >> 4;
    const int wm = warp >> 1, wn = warp & 1;
    const int rowBase = blockIdx.y * 128;     // batch rows
    const int colBase = blockIdx.x * 64;
    const int gate = blockIdx.z;

    const float* W = (gate == 0) ? Wi : (gate == 1) ? Wo : Wu;
    const float* U = (gate == 0) ? Ui : (gate == 1) ? Uo : Uu;

    float acc[2][4][4];
#pragma unroll
    for (int mi = 0; mi < 2; mi++)
#pragma unroll
        for (int ni = 0; ni < 4; ni++)
#pragma unroll
            for (int e = 0; e < 4; e++) acc[mi][ni][e] = 0.0f;

    const int rA0 = tid >> 2, cA0 = tid & 3;
    const int rA1 = rA0 + 64;
    const int rB  = tid >> 2, cB = tid & 3;
    float4 aS[2][2], bS[2];

    auto LDG = [&](int c) {
        const int k0 = c * KCH;
        {
            const int kk = k0 + cA0 * 8;
            const float* p0 = (k0 < SIZE_)
                ? zn + (size_t)(rowBase + rA0) * (NCH * SIZE_) + kk        // z0 row
                : ht + (size_t)(rowBase + rA0) * CH + (kk - SIZE_);
            aS[0][0] = *reinterpret_cast<const float4*>(p0);
            aS[0][1] = *reinterpret_cast<const float4*>(p0 + 4);
            const float* p1 = (k0 < SIZE_)
                ? zn + (size_t)(rowBase + rA1) * (NCH * SIZE_) + kk
                : ht + (size_t)(rowBase + rA1) * CH + (kk - SIZE_);
            aS[1][0] = *reinterpret_cast<const float4*>(p1);
            aS[1][1] = *reinterpret_cast<const float4*>(p1 + 4);
        }
        {
            const int kk = k0 + cB * 8;
            const float* p = (k0 < SIZE_)
                ? W + (size_t)(colBase + rB) * SIZE_ + kk
                : U + (size_t)(colBase + rB) * CH + (kk - SIZE_);
            bS[0] = *reinterpret_cast<const float4*>(p);
            bS[1] = *reinterpret_cast<const float4*>(p + 4);
        }
    };
    auto STS = [&](int buf) {
        const uint32_t a0 = sb + buf * STG_BYTES;
        sts128(a0 + swz(rA0, cA0),
               packh(aS[0][0].x, aS[0][0].y), packh(aS[0][0].z, aS[0][0].w),
               packh(aS[0][1].x, aS[0][1].y), packh(aS[0][1].z, aS[0][1].w));
        sts128(a0 + swz(rA1, cA0),
               packh(aS[1][0].x, aS[1][0].y), packh(aS[1][0].z, aS[1][0].w),
               packh(aS[1][1].x, aS[1][1].y), packh(aS[1][1].z, aS[1][1].w));
        sts128(a0 + 8192 + swz(rB, cB),
               packh(bS[0].x, bS[0].y), packh(bS[0].z, bS[0].w),
               packh(bS[1].x, bS[1].y), packh(bS[1].z, bS[1].w));
    };

    LDG(0);
    STS(0);
    LDG(1);
    __syncthreads();

    for (int c = 0; c < NITER; c++) {
        const int buf = c & 1;
        if (c + 1 < NITER) STS(buf ^ 1);
        if (c + 2 < NITER) LDG(c + 2);

        const uint32_t smA = sb + buf * STG_BYTES;
        const uint32_t smB = smA + 8192;
#pragma unroll
        for (int ks = 0; ks < 2; ks++) {
            unsigned af[2][4];
#pragma unroll
            for (int mi = 0; mi < 2; mi++) {
                const int m = wm * 32 + mi * 16 + l8 * 8 + r;
                ldsm4(af[mi], smA + swz(m, 2 * ks + l16));
            }
            unsigned bf[4][2];
#pragma unroll
            for (int p = 0; p < 2; p++) {
                const int n = wn * 32 + p * 16 + l16 * 8 + r;
                unsigned tmp[4];
                ldsm4(tmp, smB + swz(n, 2 * ks + l8));
                bf[2 * p][0] = tmp[0]; bf[2 * p][1] = tmp[1];
                bf[2 * p + 1][0] = tmp[2]; bf[2 * p + 1][1] = tmp[3];
            }
#pragma unroll
            for (int mi = 0; mi < 2; mi++)
#pragma unroll
                for (int ni = 0; ni < 4; ni++) mma16(acc[mi][ni], af[mi], bf[ni]);
        }
        __syncthreads();
    }

    // store raw logits
    float* lg = g_logits + (size_t)gate * B_ * CH;
#pragma unroll
    for (int ni = 0; ni < 4; ni++) {
        const int colG = colBase + wn * 32 + ni * 8 + 2 * t;
#pragma unroll
        for (int mi = 0; mi < 2; mi++) {
            const int rb0 = rowBase + wm * 32 + mi * 16 + g;
            const int rb1 = rb0 + 8;
            float2 v0; v0.x = acc[mi][ni][0]; v0.y = acc[mi][ni][1];
            float2 v1; v1.x = acc[mi][ni][2]; v1.y = acc[mi][ni][3];
            *reinterpret_cast<float2*>(lg + (size_t)rb0 * CH + colG) = v0;
            *reinterpret_cast<float2*>(lg + (size_t)rb1 * CH + colG) = v1;
        }
    }
}

// ---------------------------------------------------------------------------
// Kernel 4: fuse — gating + writeback
// ---------------------------------------------------------------------------
__global__ void __launch_bounds__(256)
fuse_kernel(const float* __restrict__ bi, const float* __restrict__ bo,
            const float* __restrict__ bu, float* __restrict__ out) {
    const int b = blockIdx.x;
    const int c = threadIdx.x;
    const size_t idx = (size_t)b * CH + c;
    const float iv = sigf(g_logits[idx] + bi[c]);
    const float ov = sigf(g_logits[(size_t)B_ * CH + idx] + bo[c]);
    const float uv = tanhf(g_logits[2 * (size_t)B_ * CH + idx] + bu[c]);
    const float cj = iv * uv + g_fc[idx];
    out[(size_t)b * SIZE_ + c]      = ov * tanhf(cj);
    out[(size_t)b * SIZE_ + CH + c] = cj;
}

extern "C" void kernel_launch(void* const* d_in, const int* in_sizes, int n_in,
                              void* d_out, int out_size) {
    (void)in_sizes; (void)n_in; (void)out_size;
    const float* zn = (const float*)d_in[0];   // z_node     (B, N, 512)
    const float* zc = (const float*)d_in[1];   // z_children (B, N, 512)
    const float* Wi = (const float*)d_in[2];
    const float* Ui = (const float*)d_in[3];
    const float* bi = (const float*)d_in[4];
    const float* Wf = (const float*)d_in[5];
    const float* Uf = (const float*)d_in[6];
    const float* bf = (const float*)d_in[7];
    const float* Wo = (const float*)d_in[8];
    const float* Uo = (const float*)d_in[9];
    const float* bo = (const float*)d_in[10];
    const float* Wu = (const float*)d_in[11];
    const float* Uu = (const float*)d_in[12];
    const float* bu = (const float*)d_in[13];

    float* out = (float*)d_out;                       // (B, 512) : [h_j | c_j]
    float* ht  = out + (size_t)B_ * SIZE_;            // (B, 256) : h_tilde

    // one-time resource setup (no device allocations: streams/events are
    // host-side resources; smem attr as in prior rounds)
    static cudaStream_t sB = nullptr;
    static cudaEvent_t evFork = nullptr, evB = nullptr;
    if (sB == nullptr) {
        cudaFuncSetAttribute(fgate_kernel, cudaFuncAttributeMaxDynamicSharedMemorySize,
                             2 * FG_STG2);
        cudaStreamCreateWithFlags(&sB, cudaStreamNonBlocking);
        cudaEventCreateWithFlags(&evFork, cudaEventDisableTiming);
        cudaEventCreateWithFlags(&evB, cudaEventDisableTiming);
    }

    // Fork: branch B (htilde -> iou) runs concurrently with branch A
    // (wcvt -> fgate) on the capture-origin (default) stream.
    cudaEventRecord(evFork, 0);
    cudaStreamWaitEvent(sB, evFork, 0);

    // branch B
    htilde_kernel<<<B_, 256, 0, sB>>>(zc, ht);
    iou_gemm_kernel<<<dim3(CH / 64, B_ / 128, 3), 256, 0, sB>>>(zn, ht, Wi, Ui, Wo, Uo, Wu, Uu);
    cudaEventRecord(evB, sB);

    // branch A (default stream)
    wcvt_kernel<<<CH, 256>>>(Wf, Uf);
    fgate_kernel<<<dim3(2, B_ * NCH / 128), 256, 2 * FG_STG2>>>(zn, zc, bf);

    // Join: fuse needs g_fc (fgate, stream 0) and g_logits (iou, stream B)
    cudaStreamWaitEvent(0, evB, 0);
    fuse_kernel<<<B_, 256>>>(bi, bo, bu, out);
}

// round 17
// speedup vs baseline: 1.4153x; 1.4153x over previous
#include <cuda_runtime.h>
#include <cuda_fp16.h>
#include <cstdint>

#define B_    4096
#define NCH   32
#define SIZE_ 512
#define CH    256
#define KTOT  768
#define KCH   32
#define NITER (KTOT / KCH)   // 24 (iou kernel)
#define KCH2  64
#define NIT2  (KTOT / KCH2)  // 12 (fgate kernel)

// scratch
__device__ float g_fc[B_ * CH];                 // sum_n sigmoid(f)*c_k
__device__ float g_logits[3 * B_ * CH];         // i/o/u raw logits
__device__ __half g_wfh[CH * KTOT];             // fp16 packed [Wf | Uf]  [256][768]

// ---------------------------------------------------------------------------
// helpers
// ---------------------------------------------------------------------------
__device__ __forceinline__ float sigf(float x) { return 1.0f / (1.0f + __expf(-x)); }
// fast tanh via exp: tanh(x) = 2*sigmoid(2x) - 1  (|err| < 1e-6 abs)
__device__ __forceinline__ float tanhfast(float x) {
    return 2.0f / (1.0f + __expf(-2.0f * x)) - 1.0f;
}

__device__ __forceinline__ uint32_t s2u(const void* p) {
    uint32_t a;
    asm("{ .reg .u64 t; cvta.to.shared.u64 t, %1; cvt.u32.u64 %0, t; }" : "=r"(a) : "l"(p));
    return a;
}
__device__ __forceinline__ unsigned packh(float lo, float hi) {
    __half2 h = __floats2half2_rn(lo, hi);
    return *reinterpret_cast<unsigned*>(&h);
}
__device__ __forceinline__ void cp16(uint32_t dst, const void* src) {
    asm volatile("cp.async.cg.shared.global [%0], [%1], 16;" :: "r"(dst), "l"(src) : "memory");
}
__device__ __forceinline__ void cp_commit() {
    asm volatile("cp.async.commit_group;" ::: "memory");
}
__device__ __forceinline__ void cp_wait0() {
    asm volatile("cp.async.wait_group 0;" ::: "memory");
}
__device__ __forceinline__ void ldsm4(unsigned* r, uint32_t addr) {
    asm volatile("ldmatrix.sync.aligned.m8n8.x4.shared.b16 {%0,%1,%2,%3}, [%4];"
                 : "=r"(r[0]), "=r"(r[1]), "=r"(r[2]), "=r"(r[3]) : "r"(addr));
}
__device__ __forceinline__ void sts128(uint32_t addr, unsigned a, unsigned b, unsigned c, unsigned d) {
    asm volatile("st.shared.v4.b32 [%0], {%1,%2,%3,%4};"
                 :: "r"(addr), "r"(a), "r"(b), "r"(c), "r"(d) : "memory");
}
__device__ __forceinline__ void mma16(float* d, const unsigned* a, const unsigned* b) {
    asm volatile(
        "mma.sync.aligned.m16n8k16.row.col.f32.f16.f16.f32 "
        "{%0,%1,%2,%3}, {%4,%5,%6,%7}, {%8,%9}, {%0,%1,%2,%3};\n"
        : "+f"(d[0]), "+f"(d[1]), "+f"(d[2]), "+f"(d[3])
        : "r"(a[0]), "r"(a[1]), "r"(a[2]), "r"(a[3]), "r"(b[0]), "r"(b[1]));
}

// 64B-row swizzle (iou kernel)
__device__ __forceinline__ uint32_t swz(int row, int ch) {
    return (uint32_t)row * 64u + ((uint32_t)(ch ^ ((row >> 1) & 3)) << 4);
}
// 128B-row swizzle (fgate kernel): classic SW128 16B-chunk xor
__device__ __forceinline__ uint32_t swz128(int row, int ch) {
    return (uint32_t)row * 128u + ((uint32_t)(ch ^ (row & 7)) << 4);
}

// ---------------------------------------------------------------------------
// Kernel 0: pack + convert f-gate weights to fp16
// ---------------------------------------------------------------------------
__global__ void __launch_bounds__(256) wcvt_kernel(const float* __restrict__ Wf,
                                                   const float* __restrict__ Uf) {
    const int r = blockIdx.x;
    for (int it = 0; it < 3; it++) {
        const int k = it * 256 + threadIdx.x;
        const float v = (k < SIZE_) ? Wf[(size_t)r * SIZE_ + k]
                                    : Uf[(size_t)r * CH + (k - SIZE_)];
        g_wfh[(size_t)r * KTOT + k] = __float2half_rn(v);
    }
}

// ---------------------------------------------------------------------------
// Kernel 1: h_tilde[b][c] = sum_n z_children[b][n][c]   (exact fp32)
// ---------------------------------------------------------------------------
__global__ void __launch_bounds__(256) htilde_kernel(const float* __restrict__ zc,
                                                     float* __restrict__ ht) {
    const int b = blockIdx.x;
    const int c = threadIdx.x;
    const float* p = zc + (size_t)b * NCH * SIZE_ + c;
    float s = 0.0f;
#pragma unroll
    for (int n = 0; n < NCH; n++) s += p[(size_t)n * SIZE_];
    ht[(size_t)b * CH + c] = s;
}

// ---------------------------------------------------------------------------
// Kernel 2: f-gate GEMM (131072 x 768 @ 768 x 256) fp16 + fused child
// reduction. EXACT R13 version (best fgate measured: 203us).
// CTA tile M=128 x N=128; K-chunk 64 (12 barriers). 256 threads, 8 warps,
// warp tile 64x32; 2 CTAs/SM.
// ---------------------------------------------------------------------------
#define FG_STG2 32768   // per stage: A 128x128B (16KB) + B 128x128B (16KB)

__global__ void __launch_bounds__(256, 2)
fgate_kernel(const float* __restrict__ zn, const float* __restrict__ zc,
             const float* __restrict__ bfv) {
    extern __shared__ char smem[];
    const uint32_t sb = s2u(smem);

    const int tid  = threadIdx.x;
    const int warp = tid >> 5, lane = tid & 31;
    const int g = lane >> 2, t = lane & 3;
    const int r = lane & 7, l8 = (lane >> 3) & 1, l16 = lane >> 4;
    const int wm = warp >> 2, wn = warp & 3;
    const int rowBase = blockIdx.y * 128;     // child-rows (b*32+n)
    const int colBase = blockIdx.x * 128;     // gate cols

    float acc[4][4][4];
#pragma unroll
    for (int mi = 0; mi < 4; mi++)
#pragma unroll
        for (int ni = 0; ni < 4; ni++)
#pragma unroll
            for (int e = 0; e < 4; e++) acc[mi][ni][e] = 0.0f;

    // staging geometry: unit = 16B fp16 = 8 fp32; rows tRow + 32*i, chunk tCh
    const int tRow = tid >> 3, tCh = tid & 7;
    float4 aS[4][2];

    auto LDG_A = [&](int c) {
        const int kk = c * KCH2 + tCh * 8;
#pragma unroll
        for (int i = 0; i < 4; i++) {
            const int row = rowBase + tRow + 32 * i;
            const float* p = (kk < SIZE_)
                ? zn + (size_t)row * SIZE_ + kk
                : zc + (size_t)row * SIZE_ + (kk - SIZE_);   // h_k
            aS[i][0] = *reinterpret_cast<const float4*>(p);
            aS[i][1] = *reinterpret_cast<const float4*>(p + 4);
        }
    };
    auto STS_A = [&](int buf) {
        const uint32_t a0 = sb + buf * FG_STG2;
#pragma unroll
        for (int i = 0; i < 4; i++) {
            sts128(a0 + swz128(tRow + 32 * i, tCh),
                   packh(aS[i][0].x, aS[i][0].y), packh(aS[i][0].z, aS[i][0].w),
                   packh(aS[i][1].x, aS[i][1].y), packh(aS[i][1].z, aS[i][1].w));
        }
    };
    auto CP_B = [&](int c, int buf) {
        const uint32_t smB = sb + buf * FG_STG2 + 16384;
        const int kk = c * KCH2 + tCh * 8;
#pragma unroll
        for (int i = 0; i < 4; i++) {
            const int row = tRow + 32 * i;
            cp16(smB + swz128(row, tCh), &g_wfh[(size_t)(colBase + row) * KTOT + kk]);
        }
    };

    auto DO_KS = [&](uint32_t smA, uint32_t smB, int ks) {
        unsigned af[4][4];
#pragma unroll
        for (int mi = 0; mi < 4; mi++) {
            const int m = wm * 64 + mi * 16 + l8 * 8 + r;
            ldsm4(af[mi], smA + swz128(m, 2 * ks + l16));
        }
        unsigned bf[4][2];
#pragma unroll
        for (int p = 0; p < 2; p++) {
            const int n = wn * 32 + p * 16 + l16 * 8 + r;
            unsigned tmp[4];
            ldsm4(tmp, smB + swz128(n, 2 * ks + l8));
            bf[2 * p][0] = tmp[0]; bf[2 * p][1] = tmp[1];
            bf[2 * p + 1][0] = tmp[2]; bf[2 * p + 1][1] = tmp[3];
        }
#pragma unroll
        for (int mi = 0; mi < 4; mi++)
#pragma unroll
            for (int ni = 0; ni < 4; ni++) mma16(acc[mi][ni], af[mi], bf[ni]);
    };

    // prologue: chunk0 -> stage0, chunk1 A -> regs
    CP_B(0, 0); cp_commit();
    LDG_A(0);
    STS_A(0);
    LDG_A(1);
    cp_wait0();
    __syncthreads();

    for (int c = 0; c < NIT2; c++) {
        const int buf = c & 1;
        if (c + 1 < NIT2) {
            STS_A(buf ^ 1);          // regs loaded during previous chunk
            CP_B(c + 1, buf ^ 1);
        }
        cp_commit();

        const uint32_t smA = sb + buf * FG_STG2;
        const uint32_t smB = smA + 16384;
        DO_KS(smA, smB, 0);
        if (c + 2 < NIT2) LDG_A(c + 2);   // latency hidden by remaining 3 ks
        DO_KS(smA, smB, 1);
        DO_KS(smA, smB, 2);
        DO_KS(smA, smB, 3);

        cp_wait0();
        __syncthreads();
    }

    // ---- Epilogue: sigmoid(+bias) * c_k, reduce over the 32 children ----
#pragma unroll
    for (int bb2 = 0; bb2 < 2; bb2++) {
        const int bGlob = blockIdx.y * 4 + wm * 2 + bb2;
#pragma unroll
        for (int ni = 0; ni < 4; ni++) {
            const int colG = colBase + wn * 32 + ni * 8 + 2 * t;
            const float2 bias = *reinterpret_cast<const float2*>(bfv + colG);
            float p0 = 0.0f, p1 = 0.0f;
#pragma unroll
            for (int ml = 0; ml < 2; ml++) {
                const int mi = bb2 * 2 + ml;
                const int n0 = ml * 16 + g, n1 = n0 + 8;
                const float2 ck0 = *reinterpret_cast<const float2*>(
                    zc + (size_t)(bGlob * NCH + n0) * SIZE_ + CH + colG);
                const float2 ck1 = *reinterpret_cast<const float2*>(
                    zc + (size_t)(bGlob * NCH + n1) * SIZE_ + CH + colG);
                p0 += sigf(acc[mi][ni][0] + bias.x) * ck0.x + sigf(acc[mi][ni][2] + bias.x) * ck1.x;
                p1 += sigf(acc[mi][ni][1] + bias.y) * ck0.y + sigf(acc[mi][ni][3] + bias.y) * ck1.y;
            }
#pragma unroll
            for (int s = 4; s < 32; s <<= 1) {
                p0 += __shfl_xor_sync(0xffffffffu, p0, s);
                p1 += __shfl_xor_sync(0xffffffffu, p1, s);
            }
            if (g == 0) {
                float2 v; v.x = p0; v.y = p1;
                *reinterpret_cast<float2*>(g_fc + (size_t)bGlob * CH + colG) = v;
            }
        }
    }
}

// ---------------------------------------------------------------------------
// Kernel 3: i/o/u logits (proven R8/R11 version):
// [z0 | h_tilde] (4096x768) @ (768x256) per gate; gate = blockIdx.z.
// ---------------------------------------------------------------------------
#define STG_BYTES 12288

__global__ void __launch_bounds__(256, 2)
iou_gemm_kernel(const float* __restrict__ zn, const float* __restrict__ ht,
                const float* __restrict__ Wi, const float* __restrict__ Ui,
                const float* __restrict__ Wo, const float* __restrict__ Uo,
                const float* __restrict__ Wu, const float* __restrict__ Uu) {
    __shared__ char smem[2 * STG_BYTES];
    const uint32_t sb = s2u(smem);

    const int tid  = threadIdx.x;
    const int warp = tid >> 5, lane = tid & 31;
    const int g = lane >> 2, t = lane & 3;
    const int r = lane & 7, l8 = (lane >> 3) & 1, l16 = lane >> 4;
    const int wm = warp >> 1, wn = warp & 1;
    const int rowBase = blockIdx.y * 128;     // batch rows
    const int colBase = blockIdx.x * 64;
    const int gate = blockIdx.z;

    const float* W = (gate == 0) ? Wi : (gate == 1) ? Wo : Wu;
    const float* U = (gate == 0) ? Ui : (gate == 1) ? Uo : Uu;

    float acc[2][4][4];
#pragma unroll
    for (int mi = 0; mi < 2; mi++)
#pragma unroll
        for (int ni = 0; ni < 4; ni++)
#pragma unroll
            for (int e = 0; e < 4; e++) acc[mi][ni][e] = 0.0f;

    const int rA0 = tid >> 2, cA0 = tid & 3;
    const int rA1 = rA0 + 64;
    const int rB  = tid >> 2, cB = tid & 3;
    float4 aS[2][2], bS[2];

    auto LDG = [&](int c) {
        const int k0 = c * KCH;
        {
            const int kk = k0 + cA0 * 8;
            const float* p0 = (k0 < SIZE_)
                ? zn + (size_t)(rowBase + rA0) * (NCH * SIZE_) + kk        // z0 row
                : ht + (size_t)(rowBase + rA0) * CH + (kk - SIZE_);
            aS[0][0] = *reinterpret_cast<const float4*>(p0);
            aS[0][1] = *reinterpret_cast<const float4*>(p0 + 4);
            const float* p1 = (k0 < SIZE_)
                ? zn + (size_t)(rowBase + rA1) * (NCH * SIZE_) + kk
                : ht + (size_t)(rowBase + rA1) * CH + (kk - SIZE_);
            aS[1][0] = *reinterpret_cast<const float4*>(p1);
            aS[1][1] = *reinterpret_cast<const float4*>(p1 + 4);
        }
        {
            const int kk = k0 + cB * 8;
            const float* p = (k0 < SIZE_)
                ? W + (size_t)(colBase + rB) * SIZE_ + kk
                : U + (size_t)(colBase + rB) * CH + (kk - SIZE_);
            bS[0] = *reinterpret_cast<const float4*>(p);
            bS[1] = *reinterpret_cast<const float4*>(p + 4);
        }
    };
    auto STS = [&](int buf) {
        const uint32_t a0 = sb + buf * STG_BYTES;
        sts128(a0 + swz(rA0, cA0),
               packh(aS[0][0].x, aS[0][0].y), packh(aS[0][0].z, aS[0][0].w),
               packh(aS[0][1].x, aS[0][1].y), packh(aS[0][1].z, aS[0][1].w));
        sts128(a0 + swz(rA1, cA0),
               packh(aS[1][0].x, aS[1][0].y), packh(aS[1][0].z, aS[1][0].w),
               packh(aS[1][1].x, aS[1][1].y), packh(aS[1][1].z, aS[1][1].w));
        sts128(a0 + 8192 + swz(rB, cB),
               packh(bS[0].x, bS[0].y), packh(bS[0].z, bS[0].w),
               packh(bS[1].x, bS[1].y), packh(bS[1].z, bS[1].w));
    };

    LDG(0);
    STS(0);
    LDG(1);
    __syncthreads();

    for (int c = 0; c < NITER; c++) {
        const int buf = c & 1;
        if (c + 1 < NITER) STS(buf ^ 1);
        if (c + 2 < NITER) LDG(c + 2);

        const uint32_t smA = sb + buf * STG_BYTES;
        const uint32_t smB = smA + 8192;
#pragma unroll
        for (int ks = 0; ks < 2; ks++) {
            unsigned af[2][4];
#pragma unroll
            for (int mi = 0; mi < 2; mi++) {
                const int m = wm * 32 + mi * 16 + l8 * 8 + r;
                ldsm4(af[mi], smA + swz(m, 2 * ks + l16));
            }
            unsigned bf[4][2];
#pragma unroll
            for (int p = 0; p < 2; p++) {
                const int n = wn * 32 + p * 16 + l16 * 8 + r;
                unsigned tmp[4];
                ldsm4(tmp, smB + swz(n, 2 * ks + l8));
                bf[2 * p][0] = tmp[0]; bf[2 * p][1] = tmp[1];
                bf[2 * p + 1][0] = tmp[2]; bf[2 * p + 1][1] = tmp[3];
            }
#pragma unroll
            for (int mi = 0; mi < 2; mi++)
#pragma unroll
                for (int ni = 0; ni < 4; ni++) mma16(acc[mi][ni], af[mi], bf[ni]);
        }
        __syncthreads();
    }

    // store raw logits
    float* lg = g_logits + (size_t)gate * B_ * CH;
#pragma unroll
    for (int ni = 0; ni < 4; ni++) {
        const int colG = colBase + wn * 32 + ni * 8 + 2 * t;
#pragma unroll
        for (int mi = 0; mi < 2; mi++) {
            const int rb0 = rowBase + wm * 32 + mi * 16 + g;
            const int rb1 = rb0 + 8;
            float2 v0; v0.x = acc[mi][ni][0]; v0.y = acc[mi][ni][1];
            float2 v1; v1.x = acc[mi][ni][2]; v1.y = acc[mi][ni][3];
            *reinterpret_cast<float2*>(lg + (size_t)rb0 * CH + colG) = v0;
            *reinterpret_cast<float2*>(lg + (size_t)rb1 * CH + colG) = v1;
        }
    }
}

// ---------------------------------------------------------------------------
// Kernel 4: fuse — gating + writeback. 4 elements/thread (float4), fast tanh.
// grid = B_/4 blocks x 256 threads; block handles 4 batches x 256 cols.
// ---------------------------------------------------------------------------
__global__ void __launch_bounds__(256)
fuse_kernel(const float* __restrict__ bi, const float* __restrict__ bo,
            const float* __restrict__ bu, float* __restrict__ out) {
    const int tid = threadIdx.x;
    const int bb  = tid >> 6;                  // 0..3 batch within block
    const int c4  = (tid & 63) << 2;           // col group of 4
    const int b   = blockIdx.x * 4 + bb;
    const size_t idx = (size_t)b * CH + c4;

    const float4 li = *reinterpret_cast<const float4*>(g_logits + idx);
    const float4 lo = *reinterpret_cast<const float4*>(g_logits + (size_t)B_ * CH + idx);
    const float4 lu = *reinterpret_cast<const float4*>(g_logits + 2 * (size_t)B_ * CH + idx);
    const float4 fc = *reinterpret_cast<const float4*>(g_fc + idx);
    const float4 vb_i = *reinterpret_cast<const float4*>(bi + c4);
    const float4 vb_o = *reinterpret_cast<const float4*>(bo + c4);
    const float4 vb_u = *reinterpret_cast<const float4*>(bu + c4);

    float4 hv, cv;
    {
        const float cj = sigf(li.x + vb_i.x) * tanhfast(lu.x + vb_u.x) + fc.x;
        hv.x = sigf(lo.x + vb_o.x) * tanhfast(cj);  cv.x = cj;
    }
    {
        const float cj = sigf(li.y + vb_i.y) * tanhfast(lu.y + vb_u.y) + fc.y;
        hv.y = sigf(lo.y + vb_o.y) * tanhfast(cj);  cv.y = cj;
    }
    {
        const float cj = sigf(li.z + vb_i.z) * tanhfast(lu.z + vb_u.z) + fc.z;
        hv.z = sigf(lo.z + vb_o.z) * tanhfast(cj);  cv.z = cj;
    }
    {
        const float cj = sigf(li.w + vb_i.w) * tanhfast(lu.w + vb_u.w) + fc.w;
        hv.w = sigf(lo.w + vb_o.w) * tanhfast(cj);  cv.w = cj;
    }
    *reinterpret_cast<float4*>(out + (size_t)b * SIZE_ + c4)      = hv;
    *reinterpret_cast<float4*>(out + (size_t)b * SIZE_ + CH + c4) = cv;
}

extern "C" void kernel_launch(void* const* d_in, const int* in_sizes, int n_in,
                              void* d_out, int out_size) {
    (void)in_sizes; (void)n_in; (void)out_size;
    const float* zn = (const float*)d_in[0];   // z_node     (B, N, 512)
    const float* zc = (const float*)d_in[1];   // z_children (B, N, 512)
    const float* Wi = (const float*)d_in[2];
    const float* Ui = (const float*)d_in[3];
    const float* bi = (const float*)d_in[4];
    const float* Wf = (const float*)d_in[5];
    const float* Uf = (const float*)d_in[6];
    const float* bf = (const float*)d_in[7];
    const float* Wo = (const float*)d_in[8];
    const float* Uo = (const float*)d_in[9];
    const float* bo = (const float*)d_in[10];
    const float* Wu = (const float*)d_in[11];
    const float* Uu = (const float*)d_in[12];
    const float* bu = (const float*)d_in[13];

    float* out = (float*)d_out;                       // (B, 512) : [h_j | c_j]
    float* ht  = out + (size_t)B_ * SIZE_;            // (B, 256) : h_tilde

    static bool attr_set = false;
    if (!attr_set) {
        cudaFuncSetAttribute(fgate_kernel, cudaFuncAttributeMaxDynamicSharedMemorySize,
                             2 * FG_STG2);
        attr_set = true;
    }

    // R13 launch order (serial, single stream); fgate is launch #4 (ncu slot)
    wcvt_kernel<<<CH, 256>>>(Wf, Uf);
    htilde_kernel<<<B_, 256>>>(zc, ht);
    iou_gemm_kernel<<<dim3(CH / 64, B_ / 128, 3), 256>>>(zn, ht, Wi, Ui, Wo, Uo, Wu, Uu);
    fgate_kernel<<<dim3(2, B_ * NCH / 128), 256, 2 * FG_STG2>>>(zn, zc, bf);
    fuse_kernel<<<B_ / 4, 256>>>(bi, bo, bu, out);
}